// round 6
// baseline (speedup 1.0000x reference)
#include <cuda_runtime.h>

// ---------------- problem constants ----------------
#define BB    8
#define SEQ   32768
#define HH    96
#define GG    384        // 4*HH
#define KW    16         // progress granularity (timesteps)
#define HC    256        // head chunk
#define NT    384        // threads per CTA
#define PAIRS 4          // batch pairs (B2 interleave)

typedef unsigned long long ull;

// ---------------- scratch (device globals; allocation banned) ----------------
__device__ float g_h0seq[(size_t)BB * SEQ * HH];
__device__ float g_xp1 [(size_t)BB * SEQ * GG];
__device__ float g_h1seq[(size_t)BB * SEQ * HH];

__device__ int g_prog0[PAIRS];     // layer-0 pair progress
__device__ int g_progx[2 * BB];    // xp1 progress [parity][batch]
__device__ int g_prog1[PAIRS];     // layer-1 pair progress

// ---------------- packed f32x2 helpers ----------------
__device__ __forceinline__ ull ffma2(ull a, ull b, ull c) {
    ull d;
    asm("fma.rn.f32x2 %0, %1, %2, %3;" : "=l"(d) : "l"(a), "l"(b), "l"(c));
    return d;
}
__device__ __forceinline__ ull pack2(float x, float y) {
    ull v;
    asm("mov.b64 %0, {%1, %2};" : "=l"(v) : "f"(x), "f"(y));
    return v;
}
__device__ __forceinline__ void unpack2(ull v, float& x, float& y) {
    asm("mov.b64 {%0, %1}, %2;" : "=f"(x), "=f"(y) : "l"(v));
}

// ---------------- fast activations ----------------
__device__ __forceinline__ float sigmoid_f(float x) {
    float e = __expf(-x);
    return __fdividef(1.0f, 1.0f + e);
}
__device__ __forceinline__ float tanh_f(float x) {
    float e = __expf(2.0f * x);
    return 1.0f - __fdividef(2.0f, 1.0f + e);
}

// ---------------- weight row -> registers ----------------
__device__ __forceinline__ void load_row(ull* w, const float* rowp) {
    const ulonglong2* wp = (const ulonglong2*)rowp;
#pragma unroll
    for (int k = 0; k < 24; k++) {
        ulonglong2 v = __ldg(wp + k);
        w[2 * k]     = v.x;
        w[2 * k + 1] = v.y;
    }
}

// dot(w_row, h[0..95]) + init ; h 16B aligned
__device__ __forceinline__ float dotv(const ull* __restrict__ w,
                                      const float* __restrict__ hsh,
                                      float init) {
    ull a0 = pack2(init, 0.0f);
    ull a1 = 0ull;
    const ulonglong2* h4 = (const ulonglong2*)hsh;
#pragma unroll
    for (int k = 0; k < 24; k++) {
        ulonglong2 hv = h4[k];
        a0 = ffma2(w[2 * k],     hv.x, a0);
        a1 = ffma2(w[2 * k + 1], hv.y, a1);
    }
    float x0, y0, x1, y1;
    unpack2(a0, x0, y0);
    unpack2(a1, x1, y1);
    return (x0 + x1) + (y0 + y1);
}

// ---------------- release/acquire flags ----------------
__device__ __forceinline__ void flag_store(int* p, int v) {
    asm volatile("st.release.gpu.global.b32 [%0], %1;" :: "l"(p), "r"(v) : "memory");
}
__device__ __forceinline__ int flag_load(const int* p) {
    int v;
    asm volatile("ld.acquire.gpu.global.b32 %0, [%1];" : "=r"(v) : "l"(p) : "memory");
    return v;
}
__device__ __forceinline__ void wait_ge(const int* p, int target) {
    while (flag_load(p) < target) { __nanosleep(32); }
}

__global__ void reset_kernel() {
    int i = threadIdx.x;
    if (i < PAIRS)  g_prog0[i] = 0;
    if (i < 2 * BB) g_progx[i] = 0;
    if (i < PAIRS)  g_prog1[i] = 0;
}

// =====================================================================
// Mega-kernel: 32 blocks x 384 threads, all wave-1 co-resident.
//   0..3   : layer-0 recurrence (2 batches each, interleaved)
//   4..19  : xp1 workers (2 per batch, parity interleave)
//   20..23 : layer-1 recurrence (2 batches each)
//   24..31 : head workers (1 per batch)
//
// Recurrence mapping: thread g owns gate-row g (quad=g/96, unit j=g%96)
// for BOTH batches of its pair (same weights).
// Epilogue: quad-0 threads finish batch 0 (own act = i-gate),
//           quad-1 threads finish batch 1 (own act = f-gate) — parallel.
// =====================================================================
__global__ void __launch_bounds__(NT, 1)
mega_kernel(const float* __restrict__ x,
            const float* __restrict__ Wih0, const float* __restrict__ Whh0,
            const float* __restrict__ bv0,
            const float* __restrict__ Wih1, const float* __restrict__ Whh1,
            const float* __restrict__ bv1,
            const float* __restrict__ h0in, const float* __restrict__ c0in,
            const float* __restrict__ head_w, const float* __restrict__ head_b,
            float* __restrict__ out)
{
    __shared__ __align__(16) float sh[KW * HH];   // 6 KB
    const int bid = blockIdx.x;
    const int g   = threadIdx.x;

    if (bid < PAIRS) {
        // ======== layer-0 recurrence, batches 2*bid, 2*bid+1 ========
        const int pair = bid;
        const int b0s  = 2 * pair;
        const int quad = g / HH;       // warp-uniform
        const int j    = g % HH;
        float* hs0  = sh;              // h state batch0 (96)
        float* hs1  = sh + HH;         // h state batch1 (96)
        float* gsh0 = sh + 2 * HH;     // gates batch0 (384)
        float* gsh1 = sh + 2 * HH + GG;// gates batch1 (384)

        ull w[48];
        load_row(w, Whh0 + g * HH);
        const float wih  = __ldg(&Wih0[g]);
        const float bias = __ldg(&bv0[g]);

        float cst = 0.0f;
        if (quad == 0) cst = __ldg(&c0in[j]);          // batch0 c-state
        if (quad == 1) cst = __ldg(&c0in[j]);          // batch1 c-state
        if (g < HH)            hs0[g]      = __ldg(&h0in[g]);
        if (g >= HH && g < 2*HH) hs1[g-HH] = __ldg(&h0in[g - HH]);
        __syncthreads();

        const float* xb0 = x + (size_t)b0s * SEQ;
        const float* xb1 = x + (size_t)(b0s + 1) * SEQ;
        float* hb0 = g_h0seq + (size_t)b0s * SEQ * HH;
        float* hb1 = g_h0seq + (size_t)(b0s + 1) * SEQ * HH;
        float xn0 = __ldg(&xb0[0]);
        float xn1 = __ldg(&xb1[0]);

#pragma unroll 1
        for (int t = 0; t < SEQ; t++) {
            const int tn = min(t + 1, SEQ - 1);
            float xt0 = xn0;  xn0 = __ldg(&xb0[tn]);
            float xt1 = xn1;  xn1 = __ldg(&xb1[tn]);

            float dot0 = dotv(w, hs0, fmaf(xt0, wih, bias));
            float act0 = (quad == 2) ? tanh_f(dot0) : sigmoid_f(dot0);
            gsh0[g] = act0;

            float dot1 = dotv(w, hs1, fmaf(xt1, wih, bias));
            float act1 = (quad == 2) ? tanh_f(dot1) : sigmoid_f(dot1);
            gsh1[g] = act1;
            __syncthreads();                 // all gates of both batches visible

            if (quad == 0) {                 // batch0 epilogue; act0 == iv
                float fv = gsh0[j + HH];
                float gv = gsh0[j + 2 * HH];
                float ov = gsh0[j + 3 * HH];
                cst = fmaf(fv, cst, act0 * gv);
                float hv = ov * tanh_f(cst);
                hs0[j] = hv;
                hb0[j] = hv;
            } else if (quad == 1) {          // batch1 epilogue; act1 == fv
                float iv = gsh1[j];
                float gv = gsh1[j + 2 * HH];
                float ov = gsh1[j + 3 * HH];
                cst = fmaf(act1, cst, iv * gv);
                float hv = ov * tanh_f(cst);
                hs1[j] = hv;
                hb1[j] = hv;
            }
            __syncthreads();                 // h of both batches visible
            if (((t & (KW - 1)) == (KW - 1)) && g == GG - 1)
                flag_store(&g_prog0[pair], t + 1);
            hb0 += HH;
            hb1 += HH;
        }
    } else if (bid < 20) {
        // ======== xp1 workers: 2 per batch ========
        const int i   = bid - PAIRS;
        const int b   = i >> 1;
        const int par = i & 1;

        ull w[48];
        load_row(w, Wih1 + g * HH);
        const float bias = __ldg(&bv1[g]);

        const float* hbase = g_h0seq + (size_t)b * SEQ * HH;
        float* xpb = g_xp1 + (size_t)b * SEQ * GG;

#pragma unroll 1
        for (int t0 = par * KW; t0 < SEQ; t0 += 2 * KW) {
            if (g == 0) wait_ge(&g_prog0[b >> 1], t0 + KW);
            __syncthreads();
            ((float4*)sh)[g] = ((const float4*)(hbase + (size_t)t0 * HH))[g];
            __syncthreads();
            float* xpt = xpb + (size_t)t0 * GG + g;
#pragma unroll 4
            for (int s = 0; s < KW; s++) {
                xpt[0] = dotv(w, sh + s * HH, bias);
                xpt += GG;
            }
            __syncthreads();
            if (g == 0) flag_store(&g_progx[par * BB + b], t0 + KW);
        }
    } else if (bid < 24) {
        // ======== layer-1 recurrence, batches 2*(bid-20), +1 ========
        const int pair = bid - 20;
        const int b0s  = 2 * pair;
        const int quad = g / HH;
        const int j    = g % HH;
        float* hs0  = sh;
        float* hs1  = sh + HH;
        float* gsh0 = sh + 2 * HH;
        float* gsh1 = sh + 2 * HH + GG;

        ull w[48];
        load_row(w, Whh1 + g * HH);

        float cst = 0.0f;
        if (quad == 0) cst = __ldg(&c0in[HH + j]);
        if (quad == 1) cst = __ldg(&c0in[HH + j]);
        if (g < HH)              hs0[g]      = __ldg(&h0in[HH + g]);
        if (g >= HH && g < 2*HH) hs1[g - HH] = __ldg(&h0in[HH + g - HH]);
        __syncthreads();

        const float* xpr0 = g_xp1 + (size_t)b0s * SEQ * GG + g;
        const float* xpr1 = g_xp1 + (size_t)(b0s + 1) * SEQ * GG + g;
        float* hb0 = g_h1seq + (size_t)b0s * SEQ * HH;
        float* hb1 = g_h1seq + (size_t)(b0s + 1) * SEQ * HH;

#pragma unroll 1
        for (int t0 = 0; t0 < SEQ; t0 += KW) {
            const int par = (t0 >> 4) & 1;
            if (g == 0) {
                wait_ge(&g_progx[par * BB + b0s],     t0 + KW);
                wait_ge(&g_progx[par * BB + b0s + 1], t0 + KW);
            }
            __syncthreads();

            float xn0 = xpr0[0];
            float xn1 = xpr1[0];
#pragma unroll 1
            for (int tt = 0; tt < KW; tt++) {
                const int stepoff = (tt + 1 < KW) ? GG : 0;
                float xp0 = xn0;  xn0 = xpr0[stepoff];
                float xp1 = xn1;  xn1 = xpr1[stepoff];

                float dot0 = dotv(w, hs0, xp0);
                float act0 = (quad == 2) ? tanh_f(dot0) : sigmoid_f(dot0);
                gsh0[g] = act0;

                float dot1 = dotv(w, hs1, xp1);
                float act1 = (quad == 2) ? tanh_f(dot1) : sigmoid_f(dot1);
                gsh1[g] = act1;
                __syncthreads();

                if (quad == 0) {
                    float fv = gsh0[j + HH];
                    float gv = gsh0[j + 2 * HH];
                    float ov = gsh0[j + 3 * HH];
                    cst = fmaf(fv, cst, act0 * gv);
                    float hv = ov * tanh_f(cst);
                    hs0[j] = hv;
                    hb0[j] = hv;
                } else if (quad == 1) {
                    float iv = gsh1[j];
                    float gv = gsh1[j + 2 * HH];
                    float ov = gsh1[j + 3 * HH];
                    cst = fmaf(act1, cst, iv * gv);
                    float hv = ov * tanh_f(cst);
                    hs1[j] = hv;
                    hb1[j] = hv;
                }
                __syncthreads();
                hb0 += HH;
                hb1 += HH;
                xpr0 += GG;
                xpr1 += GG;
            }
            if (g == GG - 1) flag_store(&g_prog1[pair], t0 + KW);
        }
    } else {
        // ======== head workers ========
        const int b = bid - 24;
        float4 wv[24];
        const float4* wp = (const float4*)head_w;
#pragma unroll
        for (int k = 0; k < 24; k++) wv[k] = __ldg(&wp[k]);
        const float hb0c = __ldg(&head_b[0]);
        const float* h1b = g_h1seq + (size_t)b * SEQ * HH;
        float* ob = out + (size_t)b * SEQ;

#pragma unroll 1
        for (int t0 = 0; t0 < SEQ; t0 += HC) {
            if (g == 0) wait_ge(&g_prog1[b >> 1], t0 + HC);
            __syncthreads();
            if (g < HC) {
                const float4* hp = (const float4*)(h1b + (size_t)(t0 + g) * HH);
                float acc = 0.0f;
#pragma unroll
                for (int k = 0; k < 24; k++) {
                    float4 a = hp[k];
                    acc += a.x * wv[k].x + a.y * wv[k].y + a.z * wv[k].z + a.w * wv[k].w;
                }
                ob[t0 + g] = acc + hb0c;
            }
        }
    }
}

extern "C" void kernel_launch(void* const* d_in, const int* in_sizes, int n_in,
                              void* d_out, int out_size)
{
    (void)in_sizes; (void)n_in; (void)out_size;
    const float* x      = (const float*)d_in[0];
    const float* W_ih_0 = (const float*)d_in[1];
    const float* W_hh_0 = (const float*)d_in[2];
    const float* b_0    = (const float*)d_in[3];
    const float* W_ih_1 = (const float*)d_in[4];
    const float* W_hh_1 = (const float*)d_in[5];
    const float* b_1    = (const float*)d_in[6];
    const float* h0     = (const float*)d_in[7];
    const float* c0     = (const float*)d_in[8];
    const float* head_w = (const float*)d_in[9];
    const float* head_b = (const float*)d_in[10];
    float* out = (float*)d_out;

    reset_kernel<<<1, 32>>>();
    mega_kernel<<<32, NT>>>(x, W_ih_0, W_hh_0, b_0, W_ih_1, W_hh_1, b_1,
                            h0, c0, head_w, head_b, out);
}

// round 7
// speedup vs baseline: 1.0022x; 1.0022x over previous
#include <cuda_runtime.h>

// ---------------- problem constants ----------------
#define BB    8
#define SEQ   32768
#define HH    96
#define GG    384        // 4*HH
#define KW    16         // progress granularity (timesteps)
#define HC    256        // head chunk
#define NT    384        // threads per CTA
#define PAIRS 4          // batch pairs (B2 interleave)

typedef unsigned long long ull;

// ---------------- scratch (device globals; allocation banned) ----------------
__device__ float g_h0seq[(size_t)BB * SEQ * HH];
__device__ float g_xp1 [(size_t)BB * SEQ * GG];
__device__ float g_h1seq[(size_t)BB * SEQ * HH];

__device__ int g_prog0[PAIRS];     // layer-0 pair progress
__device__ int g_progx[2 * BB];    // xp1 progress [parity][batch]
__device__ int g_prog1[PAIRS];     // layer-1 pair progress

// ---------------- packed f32x2 helpers ----------------
__device__ __forceinline__ ull ffma2(ull a, ull b, ull c) {
    ull d;
    asm("fma.rn.f32x2 %0, %1, %2, %3;" : "=l"(d) : "l"(a), "l"(b), "l"(c));
    return d;
}
__device__ __forceinline__ ull pack2(float x, float y) {
    ull v;
    asm("mov.b64 %0, {%1, %2};" : "=l"(v) : "f"(x), "f"(y));
    return v;
}
__device__ __forceinline__ void unpack2(ull v, float& x, float& y) {
    asm("mov.b64 {%0, %1}, %2;" : "=f"(x), "=f"(y) : "l"(v));
}

// ---------------- fast activations ----------------
__device__ __forceinline__ float sigmoid_f(float x) {
    float e = __expf(-x);
    return __fdividef(1.0f, 1.0f + e);
}
__device__ __forceinline__ float tanh_f(float x) {
    float e = __expf(2.0f * x);
    return 1.0f - __fdividef(2.0f, 1.0f + e);
}

// ---------------- weight row -> registers ----------------
__device__ __forceinline__ void load_row(ull* w, const float* rowp) {
    const ulonglong2* wp = (const ulonglong2*)rowp;
#pragma unroll
    for (int k = 0; k < 24; k++) {
        ulonglong2 v = __ldg(wp + k);
        w[2 * k]     = v.x;
        w[2 * k + 1] = v.y;
    }
}

// dot(w_row, h[0..95]) + init ; h 16B aligned
__device__ __forceinline__ float dotv(const ull* __restrict__ w,
                                      const float* __restrict__ hsh,
                                      float init) {
    ull a0 = pack2(init, 0.0f);
    ull a1 = 0ull;
    const ulonglong2* h4 = (const ulonglong2*)hsh;
#pragma unroll
    for (int k = 0; k < 24; k++) {
        ulonglong2 hv = h4[k];
        a0 = ffma2(w[2 * k],     hv.x, a0);
        a1 = ffma2(w[2 * k + 1], hv.y, a1);
    }
    float x0, y0, x1, y1;
    unpack2(a0, x0, y0);
    unpack2(a1, x1, y1);
    return (x0 + x1) + (y0 + y1);
}

// ---------------- release/acquire flags ----------------
__device__ __forceinline__ void flag_store(int* p, int v) {
    asm volatile("st.release.gpu.global.b32 [%0], %1;" :: "l"(p), "r"(v) : "memory");
}
__device__ __forceinline__ int flag_load(const int* p) {
    int v;
    asm volatile("ld.acquire.gpu.global.b32 %0, [%1];" : "=r"(v) : "l"(p) : "memory");
    return v;
}
__device__ __forceinline__ void wait_ge(const int* p, int target) {
    while (flag_load(p) < target) { __nanosleep(32); }
}

__global__ void reset_kernel() {
    int i = threadIdx.x;
    if (i < PAIRS)  g_prog0[i] = 0;
    if (i < 2 * BB) g_progx[i] = 0;
    if (i < PAIRS)  g_prog1[i] = 0;
}

// =====================================================================
// Mega-kernel: 32 blocks x 384 threads, all wave-1 co-resident.
//   0..3   : layer-0 recurrence (2 batches each, interleaved)
//   4..19  : xp1 workers (2 per batch, parity interleave)
//   20..23 : layer-1 recurrence (2 batches each)
//   24..31 : head workers (1 per batch)
//
// Recurrence mapping: thread g owns gate-row g (quad=g/96, unit j=g%96)
// for BOTH batches of its pair (same weights).
// Epilogue: quad-0 threads finish batch 0 (own act = i-gate),
//           quad-1 threads finish batch 1 (own act = f-gate) — parallel.
// =====================================================================
__global__ void __launch_bounds__(NT, 1)
mega_kernel(const float* __restrict__ x,
            const float* __restrict__ Wih0, const float* __restrict__ Whh0,
            const float* __restrict__ bv0,
            const float* __restrict__ Wih1, const float* __restrict__ Whh1,
            const float* __restrict__ bv1,
            const float* __restrict__ h0in, const float* __restrict__ c0in,
            const float* __restrict__ head_w, const float* __restrict__ head_b,
            float* __restrict__ out)
{
    __shared__ __align__(16) float sh[KW * HH];   // 6 KB
    const int bid = blockIdx.x;
    const int g   = threadIdx.x;

    if (bid < PAIRS) {
        // ======== layer-0 recurrence, batches 2*bid, 2*bid+1 ========
        const int pair = bid;
        const int b0s  = 2 * pair;
        const int quad = g / HH;       // warp-uniform
        const int j    = g % HH;
        float* hs0  = sh;              // h state batch0 (96)
        float* hs1  = sh + HH;         // h state batch1 (96)
        float* gsh0 = sh + 2 * HH;     // gates batch0 (384)
        float* gsh1 = sh + 2 * HH + GG;// gates batch1 (384)

        ull w[48];
        load_row(w, Whh0 + g * HH);
        const float wih  = __ldg(&Wih0[g]);
        const float bias = __ldg(&bv0[g]);

        float cst = 0.0f;
        if (quad == 0) cst = __ldg(&c0in[j]);          // batch0 c-state
        if (quad == 1) cst = __ldg(&c0in[j]);          // batch1 c-state
        if (g < HH)            hs0[g]      = __ldg(&h0in[g]);
        if (g >= HH && g < 2*HH) hs1[g-HH] = __ldg(&h0in[g - HH]);
        __syncthreads();

        const float* xb0 = x + (size_t)b0s * SEQ;
        const float* xb1 = x + (size_t)(b0s + 1) * SEQ;
        float* hb0 = g_h0seq + (size_t)b0s * SEQ * HH;
        float* hb1 = g_h0seq + (size_t)(b0s + 1) * SEQ * HH;
        float xn0 = __ldg(&xb0[0]);
        float xn1 = __ldg(&xb1[0]);

#pragma unroll 1
        for (int t = 0; t < SEQ; t++) {
            const int tn = min(t + 1, SEQ - 1);
            float xt0 = xn0;  xn0 = __ldg(&xb0[tn]);
            float xt1 = xn1;  xn1 = __ldg(&xb1[tn]);

            float dot0 = dotv(w, hs0, fmaf(xt0, wih, bias));
            float act0 = (quad == 2) ? tanh_f(dot0) : sigmoid_f(dot0);
            gsh0[g] = act0;

            float dot1 = dotv(w, hs1, fmaf(xt1, wih, bias));
            float act1 = (quad == 2) ? tanh_f(dot1) : sigmoid_f(dot1);
            gsh1[g] = act1;
            __syncthreads();                 // all gates of both batches visible

            if (quad == 0) {                 // batch0 epilogue; act0 == iv
                float fv = gsh0[j + HH];
                float gv = gsh0[j + 2 * HH];
                float ov = gsh0[j + 3 * HH];
                cst = fmaf(fv, cst, act0 * gv);
                float hv = ov * tanh_f(cst);
                hs0[j] = hv;
                hb0[j] = hv;
            } else if (quad == 1) {          // batch1 epilogue; act1 == fv
                float iv = gsh1[j];
                float gv = gsh1[j + 2 * HH];
                float ov = gsh1[j + 3 * HH];
                cst = fmaf(act1, cst, iv * gv);
                float hv = ov * tanh_f(cst);
                hs1[j] = hv;
                hb1[j] = hv;
            }
            __syncthreads();                 // h of both batches visible
            if (((t & (KW - 1)) == (KW - 1)) && g == GG - 1)
                flag_store(&g_prog0[pair], t + 1);
            hb0 += HH;
            hb1 += HH;
        }
    } else if (bid < 20) {
        // ======== xp1 workers: 2 per batch ========
        const int i   = bid - PAIRS;
        const int b   = i >> 1;
        const int par = i & 1;

        ull w[48];
        load_row(w, Wih1 + g * HH);
        const float bias = __ldg(&bv1[g]);

        const float* hbase = g_h0seq + (size_t)b * SEQ * HH;
        float* xpb = g_xp1 + (size_t)b * SEQ * GG;

#pragma unroll 1
        for (int t0 = par * KW; t0 < SEQ; t0 += 2 * KW) {
            if (g == 0) wait_ge(&g_prog0[b >> 1], t0 + KW);
            __syncthreads();
            ((float4*)sh)[g] = ((const float4*)(hbase + (size_t)t0 * HH))[g];
            __syncthreads();
            float* xpt = xpb + (size_t)t0 * GG + g;
#pragma unroll 4
            for (int s = 0; s < KW; s++) {
                xpt[0] = dotv(w, sh + s * HH, bias);
                xpt += GG;
            }
            __syncthreads();
            if (g == 0) flag_store(&g_progx[par * BB + b], t0 + KW);
        }
    } else if (bid < 24) {
        // ======== layer-1 recurrence, batches 2*(bid-20), +1 ========
        const int pair = bid - 20;
        const int b0s  = 2 * pair;
        const int quad = g / HH;
        const int j    = g % HH;
        float* hs0  = sh;
        float* hs1  = sh + HH;
        float* gsh0 = sh + 2 * HH;
        float* gsh1 = sh + 2 * HH + GG;

        ull w[48];
        load_row(w, Whh1 + g * HH);

        float cst = 0.0f;
        if (quad == 0) cst = __ldg(&c0in[HH + j]);
        if (quad == 1) cst = __ldg(&c0in[HH + j]);
        if (g < HH)              hs0[g]      = __ldg(&h0in[HH + g]);
        if (g >= HH && g < 2*HH) hs1[g - HH] = __ldg(&h0in[HH + g - HH]);
        __syncthreads();

        const float* xpr0 = g_xp1 + (size_t)b0s * SEQ * GG + g;
        const float* xpr1 = g_xp1 + (size_t)(b0s + 1) * SEQ * GG + g;
        float* hb0 = g_h1seq + (size_t)b0s * SEQ * HH;
        float* hb1 = g_h1seq + (size_t)(b0s + 1) * SEQ * HH;

#pragma unroll 1
        for (int t0 = 0; t0 < SEQ; t0 += KW) {
            const int par = (t0 >> 4) & 1;
            if (g == 0) {
                wait_ge(&g_progx[par * BB + b0s],     t0 + KW);
                wait_ge(&g_progx[par * BB + b0s + 1], t0 + KW);
            }
            __syncthreads();

            float xn0 = xpr0[0];
            float xn1 = xpr1[0];
#pragma unroll 1
            for (int tt = 0; tt < KW; tt++) {
                const int stepoff = (tt + 1 < KW) ? GG : 0;
                float xp0 = xn0;  xn0 = xpr0[stepoff];
                float xp1 = xn1;  xn1 = xpr1[stepoff];

                float dot0 = dotv(w, hs0, xp0);
                float act0 = (quad == 2) ? tanh_f(dot0) : sigmoid_f(dot0);
                gsh0[g] = act0;

                float dot1 = dotv(w, hs1, xp1);
                float act1 = (quad == 2) ? tanh_f(dot1) : sigmoid_f(dot1);
                gsh1[g] = act1;
                __syncthreads();

                if (quad == 0) {
                    float fv = gsh0[j + HH];
                    float gv = gsh0[j + 2 * HH];
                    float ov = gsh0[j + 3 * HH];
                    cst = fmaf(fv, cst, act0 * gv);
                    float hv = ov * tanh_f(cst);
                    hs0[j] = hv;
                    hb0[j] = hv;
                } else if (quad == 1) {
                    float iv = gsh1[j];
                    float gv = gsh1[j + 2 * HH];
                    float ov = gsh1[j + 3 * HH];
                    cst = fmaf(act1, cst, iv * gv);
                    float hv = ov * tanh_f(cst);
                    hs1[j] = hv;
                    hb1[j] = hv;
                }
                __syncthreads();
                hb0 += HH;
                hb1 += HH;
                xpr0 += GG;
                xpr1 += GG;
            }
            if (g == GG - 1) flag_store(&g_prog1[pair], t0 + KW);
        }
    } else {
        // ======== head workers ========
        const int b = bid - 24;
        float4 wv[24];
        const float4* wp = (const float4*)head_w;
#pragma unroll
        for (int k = 0; k < 24; k++) wv[k] = __ldg(&wp[k]);
        const float hb0c = __ldg(&head_b[0]);
        const float* h1b = g_h1seq + (size_t)b * SEQ * HH;
        float* ob = out + (size_t)b * SEQ;

#pragma unroll 1
        for (int t0 = 0; t0 < SEQ; t0 += HC) {
            if (g == 0) wait_ge(&g_prog1[b >> 1], t0 + HC);
            __syncthreads();
            if (g < HC) {
                const float4* hp = (const float4*)(h1b + (size_t)(t0 + g) * HH);
                float acc = 0.0f;
#pragma unroll
                for (int k = 0; k < 24; k++) {
                    float4 a = hp[k];
                    acc += a.x * wv[k].x + a.y * wv[k].y + a.z * wv[k].z + a.w * wv[k].w;
                }
                ob[t0 + g] = acc + hb0c;
            }
        }
    }
}

extern "C" void kernel_launch(void* const* d_in, const int* in_sizes, int n_in,
                              void* d_out, int out_size)
{
    (void)in_sizes; (void)n_in; (void)out_size;
    const float* x      = (const float*)d_in[0];
    const float* W_ih_0 = (const float*)d_in[1];
    const float* W_hh_0 = (const float*)d_in[2];
    const float* b_0    = (const float*)d_in[3];
    const float* W_ih_1 = (const float*)d_in[4];
    const float* W_hh_1 = (const float*)d_in[5];
    const float* b_1    = (const float*)d_in[6];
    const float* h0     = (const float*)d_in[7];
    const float* c0     = (const float*)d_in[8];
    const float* head_w = (const float*)d_in[9];
    const float* head_b = (const float*)d_in[10];
    float* out = (float*)d_out;

    reset_kernel<<<1, 32>>>();
    mega_kernel<<<32, NT>>>(x, W_ih_0, W_hh_0, b_0, W_ih_1, W_hh_1, b_1,
                            h0, c0, head_w, head_b, out);
}

// round 8
// speedup vs baseline: 1.6810x; 1.6774x over previous
#include <cuda_runtime.h>

// ---------------- problem constants ----------------
#define BB  8
#define SEQ 32768
#define HH  96
#define GG  384        // 4*HH
#define KW  16         // progress granularity (timesteps)
#define HC  256        // head chunk
#define NT  384        // threads per CTA

typedef unsigned long long ull;

// ---------------- scratch (device globals; allocation banned) ----------------
__device__ float g_h0seq[(size_t)BB * SEQ * HH];
__device__ float g_xp1 [(size_t)BB * SEQ * GG];
__device__ float g_h1seq[(size_t)BB * SEQ * HH];

__device__ int g_prog0[BB];
__device__ int g_progx[2 * BB];
__device__ int g_prog1[BB];

// ---------------- packed f32x2 helpers ----------------
__device__ __forceinline__ ull ffma2(ull a, ull b, ull c) {
    ull d;
    asm("fma.rn.f32x2 %0, %1, %2, %3;" : "=l"(d) : "l"(a), "l"(b), "l"(c));
    return d;
}
__device__ __forceinline__ ull fadd2(ull a, ull b) {
    ull d;
    asm("add.rn.f32x2 %0, %1, %2;" : "=l"(d) : "l"(a), "l"(b));
    return d;
}
__device__ __forceinline__ ull pack2(float x, float y) {
    ull v;
    asm("mov.b64 %0, {%1, %2};" : "=l"(v) : "f"(x), "f"(y));
    return v;
}
__device__ __forceinline__ void unpack2(ull v, float& x, float& y) {
    asm("mov.b64 {%0, %1}, %2;" : "=f"(x), "=f"(y) : "l"(v));
}

// ---------------- fast activations ----------------
__device__ __forceinline__ float sigmoid_f(float x) {
    float e = __expf(-x);
    return __fdividef(1.0f, 1.0f + e);
}
__device__ __forceinline__ float tanh_f(float x) {
    float e = __expf(2.0f * x);
    return 1.0f - __fdividef(2.0f, 1.0f + e);
}

// ---------------- weight row -> registers ----------------
__device__ __forceinline__ void load_row(ull* w, const float* rowp) {
    const ulonglong2* wp = (const ulonglong2*)rowp;
#pragma unroll
    for (int k = 0; k < 24; k++) {
        ulonglong2 v = __ldg(wp + k);
        w[2 * k]     = v.x;
        w[2 * k + 1] = v.y;
    }
}

// dot(w_row, h[0..95]) + init ; 4 independent 12-deep FFMA2 chains
__device__ __forceinline__ float dotv(const ull* __restrict__ w,
                                      const float* __restrict__ hsh,
                                      float init) {
    ull a0 = pack2(init, 0.0f);
    ull a1 = 0ull, a2 = 0ull, a3 = 0ull;
    const ulonglong2* h4 = (const ulonglong2*)hsh;
#pragma unroll
    for (int k = 0; k < 12; k++) {
        ulonglong2 hv0 = h4[2 * k];
        ulonglong2 hv1 = h4[2 * k + 1];
        a0 = ffma2(w[4 * k],     hv0.x, a0);
        a1 = ffma2(w[4 * k + 1], hv0.y, a1);
        a2 = ffma2(w[4 * k + 2], hv1.x, a2);
        a3 = ffma2(w[4 * k + 3], hv1.y, a3);
    }
    a0 = fadd2(a0, a2);
    a1 = fadd2(a1, a3);
    a0 = fadd2(a0, a1);
    float xl, xh;
    unpack2(a0, xl, xh);
    return xl + xh;
}

// ---------------- release/acquire flags ----------------
__device__ __forceinline__ void flag_store(int* p, int v) {
    asm volatile("st.release.gpu.global.b32 [%0], %1;" :: "l"(p), "r"(v) : "memory");
}
__device__ __forceinline__ int flag_load(const int* p) {
    int v;
    asm volatile("ld.acquire.gpu.global.b32 %0, [%1];" : "=r"(v) : "l"(p) : "memory");
    return v;
}
__device__ __forceinline__ void wait_ge(const int* p, int target) {
    while (flag_load(p) < target) { __nanosleep(32); }
}

__global__ void reset_kernel() {
    int i = threadIdx.x;
    if (i < BB)     g_prog0[i] = 0;
    if (i < 2 * BB) g_progx[i] = 0;
    if (i < BB)     g_prog1[i] = 0;
}

// =====================================================================
// Mega-kernel: 40 blocks x 384 threads, all wave-1 co-resident.
//   0..7   : layer-0 recurrence (1 batch each)
//   8..23  : xp1 workers (2 per batch, parity interleave)
//   24..31 : layer-1 recurrence (1 batch each)
//   32..39 : head workers (1 per batch)
//
// Recurrence: thread g owns gate-row g.  Epilogue on warps 0-3
// (all 4 SMSPs), lane<24, unit j = 24*warp + lane.
// =====================================================================
__global__ void __launch_bounds__(NT, 1)
mega_kernel(const float* __restrict__ x,
            const float* __restrict__ Wih0, const float* __restrict__ Whh0,
            const float* __restrict__ bv0,
            const float* __restrict__ Wih1, const float* __restrict__ Whh1,
            const float* __restrict__ bv1,
            const float* __restrict__ h0in, const float* __restrict__ c0in,
            const float* __restrict__ head_w, const float* __restrict__ head_b,
            float* __restrict__ out)
{
    __shared__ __align__(16) float sh[KW * HH];   // 6 KB; recurrences use sh[0..480)
    const int bid = blockIdx.x;
    const int g   = threadIdx.x;
    const int wid = g >> 5;
    const int lid = g & 31;
    const bool epi = (wid < 4) && (lid < 24);     // epilogue threads, 4 SMSPs
    const int j    = 24 * wid + lid;              // epilogue unit (valid if epi)

    if (bid < 8) {
        // ======== layer-0 recurrence, batch b ========
        const int b    = bid;
        const int quad = g / HH;                  // warp-uniform
        float* gsh = sh + HH;                     // gate activations, 384 floats

        ull w[48];
        load_row(w, Whh0 + g * HH);
        const float wih  = __ldg(&Wih0[g]);
        const float bias = __ldg(&bv0[g]);

        float c = 0.0f;
        if (epi) c = __ldg(&c0in[j]);
        if (g < HH) sh[g] = __ldg(&h0in[g]);
        __syncthreads();

        const float* xb = x + (size_t)b * SEQ;
        float* hb_t = g_h0seq + (size_t)b * SEQ * HH;
        float xnext = __ldg(&xb[0]);

#pragma unroll 1
        for (int t = 0; t < SEQ; t++) {
            float xt = xnext;
            xnext = __ldg(&xb[min(t + 1, SEQ - 1)]);

            float dot = dotv(w, sh, fmaf(xt, wih, bias));
            float act = (quad == 2) ? tanh_f(dot) : sigmoid_f(dot);
            gsh[g] = act;
            __syncthreads();                      // gates visible

            if (epi) {
                float iv = gsh[j];
                float fv = gsh[j + HH];
                float gv = gsh[j + 2 * HH];
                float ov = gsh[j + 3 * HH];
                c = fmaf(fv, c, iv * gv);
                float hval = ov * tanh_f(c);
                sh[j]   = hval;
                hb_t[j] = hval;
            }
            __syncthreads();                      // h visible
            if (((t & (KW - 1)) == (KW - 1)) && g == GG - 1)
                flag_store(&g_prog0[b], t + 1);
            hb_t += HH;
        }
    } else if (bid < 24) {
        // ======== xp1 workers: 2 per batch ========
        const int i   = bid - 8;
        const int b   = i >> 1;
        const int par = i & 1;

        ull w[48];
        load_row(w, Wih1 + g * HH);
        const float bias = __ldg(&bv1[g]);

        const float* hbase = g_h0seq + (size_t)b * SEQ * HH;
        float* xpb = g_xp1 + (size_t)b * SEQ * GG;

#pragma unroll 1
        for (int t0 = par * KW; t0 < SEQ; t0 += 2 * KW) {
            if (g == 0) wait_ge(&g_prog0[b], t0 + KW);
            __syncthreads();
            ((float4*)sh)[g] = ((const float4*)(hbase + (size_t)t0 * HH))[g];
            __syncthreads();
            float* xpt = xpb + (size_t)t0 * GG + g;
#pragma unroll 4
            for (int s = 0; s < KW; s++) {
                xpt[0] = dotv(w, sh + s * HH, bias);
                xpt += GG;
            }
            __syncthreads();
            if (g == 0) flag_store(&g_progx[par * BB + b], t0 + KW);
        }
    } else if (bid < 32) {
        // ======== layer-1 recurrence, batch b ========
        const int b    = bid - 24;
        const int quad = g / HH;
        float* gsh = sh + HH;

        ull w[48];
        load_row(w, Whh1 + g * HH);

        float c = 0.0f;
        if (epi) c = __ldg(&c0in[HH + j]);
        if (g < HH) sh[g] = __ldg(&h0in[HH + g]);
        __syncthreads();

        const float* xpr = g_xp1 + (size_t)b * SEQ * GG + g;
        float* hb_t = g_h1seq + (size_t)b * SEQ * HH;

#pragma unroll 1
        for (int t0 = 0; t0 < SEQ; t0 += KW) {
            const int par = (t0 >> 4) & 1;        // (t0/KW)&1, KW=16
            if (g == 0) wait_ge(&g_progx[par * BB + b], t0 + KW);
            __syncthreads();

            float xpn = xpr[0];
#pragma unroll 1
            for (int tt = 0; tt < KW; tt++) {
                float xp = xpn;
                xpn = xpr[(tt + 1 < KW) ? GG : 0];   // prefetch within chunk

                float dot = dotv(w, sh, xp);
                float act = (quad == 2) ? tanh_f(dot) : sigmoid_f(dot);
                gsh[g] = act;
                __syncthreads();

                if (epi) {
                    float iv = gsh[j];
                    float fv = gsh[j + HH];
                    float gv = gsh[j + 2 * HH];
                    float ov = gsh[j + 3 * HH];
                    c = fmaf(fv, c, iv * gv);
                    float hval = ov * tanh_f(c);
                    sh[j]   = hval;
                    hb_t[j] = hval;
                }
                __syncthreads();
                hb_t += HH;
                xpr  += GG;
            }
            if (g == GG - 1) flag_store(&g_prog1[b], t0 + KW);
        }
    } else {
        // ======== head workers ========
        const int b = bid - 32;
        float4 wv[24];
        const float4* wp = (const float4*)head_w;
#pragma unroll
        for (int k = 0; k < 24; k++) wv[k] = __ldg(&wp[k]);
        const float hb0 = __ldg(&head_b[0]);
        const float* h1b = g_h1seq + (size_t)b * SEQ * HH;
        float* ob = out + (size_t)b * SEQ;

#pragma unroll 1
        for (int t0 = 0; t0 < SEQ; t0 += HC) {
            if (g == 0) wait_ge(&g_prog1[b], t0 + HC);
            __syncthreads();
            if (g < HC) {
                const float4* hp = (const float4*)(h1b + (size_t)(t0 + g) * HH);
                float acc = 0.0f;
#pragma unroll
                for (int k = 0; k < 24; k++) {
                    float4 a = hp[k];
                    acc += a.x * wv[k].x + a.y * wv[k].y + a.z * wv[k].z + a.w * wv[k].w;
                }
                ob[t0 + g] = acc + hb0;
            }
        }
    }
}

extern "C" void kernel_launch(void* const* d_in, const int* in_sizes, int n_in,
                              void* d_out, int out_size)
{
    (void)in_sizes; (void)n_in; (void)out_size;
    const float* x      = (const float*)d_in[0];
    const float* W_ih_0 = (const float*)d_in[1];
    const float* W_hh_0 = (const float*)d_in[2];
    const float* b_0    = (const float*)d_in[3];
    const float* W_ih_1 = (const float*)d_in[4];
    const float* W_hh_1 = (const float*)d_in[5];
    const float* b_1    = (const float*)d_in[6];
    const float* h0     = (const float*)d_in[7];
    const float* c0     = (const float*)d_in[8];
    const float* head_w = (const float*)d_in[9];
    const float* head_b = (const float*)d_in[10];
    float* out = (float*)d_out;

    reset_kernel<<<1, 32>>>();
    mega_kernel<<<40, NT>>>(x, W_ih_0, W_hh_0, b_0, W_ih_1, W_hh_1, b_1,
                            h0, c0, head_w, head_b, out);
}